// round 9
// baseline (speedup 1.0000x reference)
#include <cuda_runtime.h>

typedef unsigned long long ull;

// ---- f32x2 packed helpers (sm_100+) ----
__device__ __forceinline__ ull pack2(float lo, float hi) {
    ull r; asm("mov.b64 %0, {%1, %2};" : "=l"(r) : "f"(lo), "f"(hi)); return r;
}
__device__ __forceinline__ ull dup2(float v) {
    ull r; asm("mov.b64 %0, {%1, %1};" : "=l"(r) : "f"(v)); return r;
}
__device__ __forceinline__ float2 unpack2(ull v) {
    float2 r; asm("mov.b64 {%0, %1}, %2;" : "=f"(r.x), "=f"(r.y) : "l"(v)); return r;
}
__device__ __forceinline__ ull fma2_(ull a, ull b, ull c) {
    ull r; asm("fma.rn.f32x2 %0, %1, %2, %3;" : "=l"(r) : "l"(a), "l"(b), "l"(c)); return r;
}
__device__ __forceinline__ ull mul2_(ull a, ull b) {
    ull r; asm("mul.rn.f32x2 %0, %1, %2;" : "=l"(r) : "l"(a), "l"(b)); return r;
}
__device__ __forceinline__ ull add2_(ull a, ull b) {
    ull r; asm("add.rn.f32x2 %0, %1, %2;" : "=l"(r) : "l"(a), "l"(b)); return r;
}
__device__ __forceinline__ ull abs2_(ull a) {
    ull r; asm("and.b64 %0, %1, 0x7FFFFFFF7FFFFFFF;" : "=l"(r) : "l"(a)); return r;
}
__device__ __forceinline__ ull neg2_(ull a) {
    ull r; asm("xor.b64 %0, %1, 0x8000000080000000;" : "=l"(r) : "l"(a)); return r;
}
__device__ __forceinline__ float tanh_approx(float x) {
    float y; asm("tanh.approx.f32 %0, %1;" : "=f"(y) : "f"(x)); return y;
}

#define C_K0 dup2(0.79788456080286536f)
#define C_KK dup2(0.79788456080286536f * 0.044715f)
#define C_A2 dup2(0.2525f)   // leaky(0.5z) = .2525 z + .2475 |z|
#define C_B2 dup2(0.2475f)
#define C_A1 dup2(0.505f)    // leaky(o)    = .505 o + .495 |o|
#define C_B1 dup2(0.495f)

// packed tanh-GELU + leaky on pre-activation pair {ch0, ch1}
__device__ __forceinline__ ull act2(ull ap) {
    ull x2 = mul2_(ap, ap);
    ull u  = mul2_(ap, fma2_(x2, C_KK, C_K0));   // k0*a*(1 + k1*a^2)
    float2 uv = unpack2(u);
    ull th = pack2(tanh_approx(uv.x), tanh_approx(uv.y));
    ull z  = fma2_(ap, th, ap);                  // a*(1+tanh) = 2*gelu
    return fma2_(z, C_A2, mul2_(abs2_(z), C_B2));
}

__device__ __forceinline__ ull shflu(ull v, int d) {
    return __shfl_up_sync(0xffffffffu, v, d);
}
__device__ __forceinline__ ull shfld(ull v, int d) {
    return __shfl_down_sync(0xffffffffu, v, d);
}

// Grid: 8192 CTAs x 512 threads. CTA = (b, cin, half-row); thread owns 2
// output pairs. Single pass: conv1+BN+GELU+leaky+Haar in registers, band
// halo via warp shuffles (smem boundary for warp edges, recompute/zeros at
// CTA/row edges), then conv2s+merge+skip+leaky -> STG. No band smem.
__global__ __launch_bounds__(512, 2)
void fused_block_wavelet_down(
    const float* __restrict__ x,      // (64, 64, 4096)
    const float* __restrict__ w1,     // (128, 1, 7)
    const float* __restrict__ g1,
    const float* __restrict__ b1,
    const float* __restrict__ m1,
    const float* __restrict__ v1,
    const float* __restrict__ w2L,    // (128, 1, 7)
    const float* __restrict__ w2H,    // (128, 1, 3)
    const float* __restrict__ wskip,  // (128, 1, 1)
    float* __restrict__ out)          // (64, 128, 4096)
{
    __shared__ float sx[2072];        // local x index t in [-12, 2060) at sx[t+12]
    __shared__ ull bndL[16][4];       // from warp w: {l30.Lb, l31.La, l31.Lb, l31.Hb}
    __shared__ ull bndR[16][4];       // from warp w: {l0.La, l0.Lb, l0.Ha, l1.La}

    const int tid  = threadIdx.x;
    const int lane = tid & 31;
    const int wrp  = tid >> 5;
    const int bx   = blockIdx.x;
    const int half = bx & 1;
    const int cin  = (bx >> 1) & 63;
    const int b    = bx >> 7;
    const int oc0  = 2 * cin;

    const float4* xr4 = reinterpret_cast<const float4*>(
        x + ((size_t)(b * 64 + cin) << 12));

    // ---- stage x half-row + 12-float halo each side ----
    {
        float4* s4 = reinterpret_cast<float4*>(sx);
        s4[3 + tid] = xr4[half * 512 + tid];          // local t = 4*tid
        if (tid < 3) {                                 // left halo t = -12..-1
            int g = half * 512 - 3 + tid;
            s4[tid] = (g >= 0) ? xr4[g] : make_float4(0, 0, 0, 0);
        } else if (tid < 6) {                          // right halo t = 2048..2059
            int i = tid - 3;
            int g = half * 512 + 512 + i;
            s4[515 + i] = (g < 1024) ? xr4[g] : make_float4(0, 0, 0, 0);
        }
    }

    // ---- phase-A weights, BN folded, packed across the channel pair ----
    ull wkp[7], biasp;
    {
        float inv0 = g1[oc0]     * rsqrtf(v1[oc0]     + 1e-5f);
        float inv1 = g1[oc0 + 1] * rsqrtf(v1[oc0 + 1] + 1e-5f);
        #pragma unroll
        for (int k = 0; k < 7; ++k)
            wkp[k] = pack2(w1[oc0 * 7 + k] * inv0, w1[oc0 * 7 + 7 + k] * inv1);
        biasp = pack2(b1[oc0]     - m1[oc0]     * inv0,
                      b1[oc0 + 1] - m1[oc0 + 1] * inv1);
    }

    __syncthreads();

    // ---- phase A: conv7(+BN) + GELU + leaky + Haar, pairs 2tid, 2tid+1 ----
    const float4* sx4 = reinterpret_cast<const float4*>(sx);
    float4 f0 = sx4[tid + 2];          // x[4tid-4 .. 4tid-1]
    float4 f1 = sx4[tid + 3];          // x[4tid   .. 4tid+3]
    float4 f2 = sx4[tid + 4];          // x[4tid+4 .. 4tid+7]
    float v[12] = {f0.x,f0.y,f0.z,f0.w, f1.x,f1.y,f1.z,f1.w,
                   f2.x,f2.y,f2.z,f2.w};                 // v[i] = x[4tid-4+i]
    ull hp[4];
    #pragma unroll
    for (int j = 0; j < 4; ++j) {
        ull a = biasp;
        #pragma unroll
        for (int k = 0; k < 7; ++k)
            a = fma2_(dup2(v[1 + j + k]), wkp[k], a);
        hp[j] = act2(a);
    }
    ull La = add2_(hp[0], hp[1]), Ha = add2_(hp[0], neg2_(hp[1]));
    ull Lb = add2_(hp[2], hp[3]), Hb = add2_(hp[2], neg2_(hp[3]));

    // ---- warp-edge boundary exchange ----
    if (lane == 30)      bndL[wrp][0] = Lb;
    else if (lane == 31) { bndL[wrp][1] = La; bndL[wrp][2] = Lb; bndL[wrp][3] = Hb; }
    if (lane == 0)       { bndR[wrp][0] = La; bndR[wrp][1] = Lb; bndR[wrp][2] = Ha; }
    else if (lane == 1)  bndR[wrp][3] = La;

    __syncthreads();

    // ---- in-warp halo via shuffles (convergent) ----
    // Window L: pairs 2tid-3..2tid+4 ; H: pairs 2tid-1..2tid+2
    ull Lf0 = shflu(Lb, 2);   // pair 2tid-3
    ull Lf1 = shflu(La, 1);   // 2tid-2
    ull Lf2 = shflu(Lb, 1);   // 2tid-1
    ull Lf5 = shfld(La, 1);   // 2tid+2
    ull Lf6 = shfld(Lb, 1);   // 2tid+3
    ull Lf7 = shfld(La, 2);   // 2tid+4
    ull Hf0 = shflu(Hb, 1);   // 2tid-1
    ull Hf3 = shfld(Ha, 1);   // 2tid+2

    // ---- edge fixups ----
    if (lane < 2) {
        if (wrp > 0) {
            if (lane == 0) {
                Lf0 = bndL[wrp-1][0]; Lf1 = bndL[wrp-1][1];
                Lf2 = bndL[wrp-1][2]; Hf0 = bndL[wrp-1][3];
            } else {
                Lf0 = bndL[wrp-1][2];
            }
        } else if (half == 0) {                  // row start: conv zero pads
            if (lane == 0) { Lf0 = 0; Lf1 = 0; Lf2 = 0; Hf0 = 0; }
            else           { Lf0 = 0; }
        } else {
            // recompute pairs -3..-1 from x halo: h at local pos -6..-1
            float inv0 = g1[oc0]     * rsqrtf(v1[oc0]     + 1e-5f);
            float inv1 = g1[oc0 + 1] * rsqrtf(v1[oc0 + 1] + 1e-5f);
            float bb0 = b1[oc0]     - m1[oc0]     * inv0;
            float bb1 = b1[oc0 + 1] - m1[oc0 + 1] * inv1;
            ull hr[6];
            #pragma unroll
            for (int t = 0; t < 6; ++t) {        // h(local -6+t), x[-9+t .. -3+t]
                float a0 = bb0, a1 = bb1;
                #pragma unroll
                for (int k = 0; k < 7; ++k) {
                    float xv = sx[3 + t + k];    // x local (-6+t)-3+k, +12 offset
                    a0 = fmaf(xv, w1[oc0 * 7 + k]     * inv0, a0);
                    a1 = fmaf(xv, w1[oc0 * 7 + 7 + k] * inv1, a1);
                }
                hr[t] = act2(pack2(a0, a1));
            }
            if (lane == 0) {
                Lf0 = add2_(hr[0], hr[1]);       // pair -3
                Lf1 = add2_(hr[2], hr[3]);       // pair -2
                Lf2 = add2_(hr[4], hr[5]);       // pair -1
                Hf0 = add2_(hr[4], neg2_(hr[5]));
            } else {
                Lf0 = add2_(hr[4], hr[5]);       // pair -1 (= 2*1-3)
            }
        }
    }
    if (lane >= 30) {
        if (wrp < 15) {
            if (lane == 31) {
                Lf5 = bndR[wrp+1][0]; Lf6 = bndR[wrp+1][1];
                Hf3 = bndR[wrp+1][2]; Lf7 = bndR[wrp+1][3];
            } else {
                Lf7 = bndR[wrp+1][0];
            }
        } else if (half == 1) {                  // row end: conv zero pads
            if (lane == 31) { Lf5 = 0; Lf6 = 0; Hf3 = 0; Lf7 = 0; }
            else            { Lf7 = 0; }
        } else {
            // recompute pairs 1024..1026: h at local pos 2048..2053
            float inv0 = g1[oc0]     * rsqrtf(v1[oc0]     + 1e-5f);
            float inv1 = g1[oc0 + 1] * rsqrtf(v1[oc0 + 1] + 1e-5f);
            float bb0 = b1[oc0]     - m1[oc0]     * inv0;
            float bb1 = b1[oc0 + 1] - m1[oc0 + 1] * inv1;
            ull hr[6];
            #pragma unroll
            for (int t = 0; t < 6; ++t) {        // h(2048+t), x[2045+t .. 2051+t]
                float a0 = bb0, a1 = bb1;
                #pragma unroll
                for (int k = 0; k < 7; ++k) {
                    float xv = sx[2057 + t + k];
                    a0 = fmaf(xv, w1[oc0 * 7 + k]     * inv0, a0);
                    a1 = fmaf(xv, w1[oc0 * 7 + 7 + k] * inv1, a1);
                }
                hr[t] = act2(pack2(a0, a1));
            }
            if (lane == 31) {
                Lf5 = add2_(hr[0], hr[1]);       // pair 1024
                Lf6 = add2_(hr[2], hr[3]);       // pair 1025
                Lf7 = add2_(hr[4], hr[5]);       // pair 1026
                Hf3 = add2_(hr[0], neg2_(hr[1]));
            } else {
                Lf7 = add2_(hr[0], hr[1]);       // pair 1024 (= 2*510+4)
            }
        }
    }

    // ---- phase B: conv7L/conv3H + merge + skip + leaky ----
    ull wHp[3], wLp[7];
    #pragma unroll
    for (int k = 0; k < 3; ++k)
        wHp[k] = pack2(w2H[oc0 * 3 + k] * 0.5f, w2H[oc0 * 3 + 3 + k] * 0.5f);
    ull yHA = mul2_(wHp[0], Hf0);
    yHA = fma2_(wHp[1], Ha, yHA);
    yHA = fma2_(wHp[2], Hb, yHA);
    ull yHB = mul2_(wHp[0], Ha);
    yHB = fma2_(wHp[1], Hb, yHB);
    yHB = fma2_(wHp[2], Hf3, yHB);

    #pragma unroll
    for (int k = 0; k < 7; ++k)
        wLp[k] = pack2(w2L[oc0 * 7 + k] * 0.5f, w2L[oc0 * 7 + 7 + k] * 0.5f);
    ull yLA = mul2_(wLp[0], Lf0);
    yLA = fma2_(wLp[1], Lf1, yLA);
    yLA = fma2_(wLp[2], Lf2, yLA);
    yLA = fma2_(wLp[3], La,  yLA);
    yLA = fma2_(wLp[4], Lb,  yLA);
    yLA = fma2_(wLp[5], Lf5, yLA);
    yLA = fma2_(wLp[6], Lf6, yLA);
    ull yLB = mul2_(wLp[0], Lf1);
    yLB = fma2_(wLp[1], Lf2, yLB);
    yLB = fma2_(wLp[2], La,  yLB);
    yLB = fma2_(wLp[3], Lb,  yLB);
    yLB = fma2_(wLp[4], Lf5, yLB);
    yLB = fma2_(wLp[5], Lf6, yLB);
    yLB = fma2_(wLp[6], Lf7, yLB);

    const ull wsp = pack2(wskip[oc0], wskip[oc0 + 1]);
    ull eA = add2_(yLA, yHA), dA = add2_(yLA, neg2_(yHA));
    ull eB = add2_(yLB, yHB), dB = add2_(yLB, neg2_(yHB));
    eA = fma2_(dup2(f1.x), wsp, eA);     // skip x[4tid+0..3] = f1
    dA = fma2_(dup2(f1.y), wsp, dA);
    eB = fma2_(dup2(f1.z), wsp, eB);
    dB = fma2_(dup2(f1.w), wsp, dB);
    eA = fma2_(eA, C_A1, mul2_(abs2_(eA), C_B1));
    dA = fma2_(dA, C_A1, mul2_(abs2_(dA), C_B1));
    eB = fma2_(eB, C_A1, mul2_(abs2_(eB), C_B1));
    dB = fma2_(dB, C_A1, mul2_(abs2_(dB), C_B1));

    float2 ea = unpack2(eA), da = unpack2(dA);
    float2 eb = unpack2(eB), db = unpack2(dB);
    float4* o0p = reinterpret_cast<float4*>(
        out + ((size_t)(b * 128 + oc0) << 12)) + half * 512 + tid;
    o0p[0]    = make_float4(ea.x, da.x, eb.x, db.x);
    o0p[1024] = make_float4(ea.y, da.y, eb.y, db.y);   // next channel row
}

extern "C" void kernel_launch(void* const* d_in, const int* in_sizes, int n_in,
                              void* d_out, int out_size) {
    const float* x     = (const float*)d_in[0];
    const float* w1    = (const float*)d_in[1];
    const float* g1    = (const float*)d_in[2];
    const float* b1    = (const float*)d_in[3];
    const float* m1    = (const float*)d_in[4];
    const float* v1    = (const float*)d_in[5];
    const float* w2L   = (const float*)d_in[6];
    const float* w2H   = (const float*)d_in[7];
    const float* wskip = (const float*)d_in[8];
    float* out = (float*)d_out;

    fused_block_wavelet_down<<<64 * 64 * 2, 512>>>(
        x, w1, g1, b1, m1, v1, w2L, w2H, wskip, out);
}

// round 10
// speedup vs baseline: 1.6337x; 1.6337x over previous
#include <cuda_runtime.h>

typedef unsigned long long ull;

// ---- f32x2 packed helpers (sm_100+) ----
__device__ __forceinline__ ull pack2(float lo, float hi) {
    ull r; asm("mov.b64 %0, {%1, %2};" : "=l"(r) : "f"(lo), "f"(hi)); return r;
}
__device__ __forceinline__ ull dup2(float v) {
    ull r; asm("mov.b64 %0, {%1, %1};" : "=l"(r) : "f"(v)); return r;
}
__device__ __forceinline__ float2 unpack2(ull v) {
    float2 r; asm("mov.b64 {%0, %1}, %2;" : "=f"(r.x), "=f"(r.y) : "l"(v)); return r;
}
__device__ __forceinline__ ull fma2_(ull a, ull b, ull c) {
    ull r; asm("fma.rn.f32x2 %0, %1, %2, %3;" : "=l"(r) : "l"(a), "l"(b), "l"(c)); return r;
}
__device__ __forceinline__ ull mul2_(ull a, ull b) {
    ull r; asm("mul.rn.f32x2 %0, %1, %2;" : "=l"(r) : "l"(a), "l"(b)); return r;
}
__device__ __forceinline__ ull add2_(ull a, ull b) {
    ull r; asm("add.rn.f32x2 %0, %1, %2;" : "=l"(r) : "l"(a), "l"(b)); return r;
}
__device__ __forceinline__ ull abs2_(ull a) {
    ull r; asm("and.b64 %0, %1, 0x7FFFFFFF7FFFFFFF;" : "=l"(r) : "l"(a)); return r;
}
__device__ __forceinline__ ull neg2_(ull a) {
    ull r; asm("xor.b64 %0, %1, 0x8000000080000000;" : "=l"(r) : "l"(a)); return r;
}
__device__ __forceinline__ float tanh_approx(float x) {
    float y; asm("tanh.approx.f32 %0, %1;" : "=f"(y) : "f"(x)); return y;
}

// packed tanh-GELU + leaky on pre-activation pair {ch0, ch1}
__device__ __forceinline__ ull act2(ull ap) {
    const ull K0 = dup2(0.79788456080286536f);
    const ull KK = dup2(0.79788456080286536f * 0.044715f);
    const ull A2 = dup2(0.2525f);   // leaky(0.5z) = .2525 z + .2475 |z|
    const ull B2 = dup2(0.2475f);
    ull x2 = mul2_(ap, ap);
    ull u  = mul2_(ap, fma2_(x2, KK, K0));       // k0*a*(1 + k1*a^2)
    float2 uv = unpack2(u);
    ull th = pack2(tanh_approx(uv.x), tanh_approx(uv.y));
    ull z  = fma2_(ap, th, ap);                  // a*(1+tanh) = 2*gelu
    return fma2_(z, A2, mul2_(abs2_(z), B2));
}

// Dynamic smem layout:
//   sx : floats 0..4103                (x[t] at sx[t+4]; zeros [0..3],[4100..4103])
//   ull arrays (base = smem+4104 as ull; all ull2 bases 16B aligned):
//     E  @ ull 0    len 1028 : even L pair 2m  at E[m+1] ; zeros E[0],E[1025],E[1026]
//     O  @ ull 1028 len 1028 : odd  L pair 2m+1 at O[m+2]; zeros O[0],O[1],O[1026]
//     HE @ ull 2056 len 1026 : even H pair 2m  at HE[m]  ; zero HE[1024]
//     HO @ ull 3082 len 1026 : odd  H pair 2m+1 at HO[m+1]; zero HO[0]
// total = 16416 + 4108*8 = 49280 bytes
#define SMEM_BYTES 49280

// One CTA per (b, cin); outputs channels 2*cin, 2*cin+1. Two phases, 2 iters
// each, 8 h / 4 pairs per thread-iter. Even/odd band split keeps every hot
// band access conflict-free at halved read redundancy.
__global__ __launch_bounds__(256, 3)
void fused_block_wavelet_down(
    const float* __restrict__ x,      // (64, 64, 4096)
    const float* __restrict__ w1,     // (128, 1, 7)
    const float* __restrict__ g1,
    const float* __restrict__ b1,
    const float* __restrict__ m1,
    const float* __restrict__ v1,
    const float* __restrict__ w2L,    // (128, 1, 7)
    const float* __restrict__ w2H,    // (128, 1, 3)
    const float* __restrict__ wskip,  // (128, 1, 1)
    float* __restrict__ out)          // (64, 128, 4096)
{
    extern __shared__ float smem[];
    float* sx = smem;
    ull* E  = reinterpret_cast<ull*>(smem + 4104);
    ull* O  = E + 1028;
    ull* HE = E + 2056;
    ull* HO = E + 3082;

    const int tid = threadIdx.x;
    const int b   = blockIdx.x >> 6;
    const int cin = blockIdx.x & 63;
    const int oc0 = 2 * cin;

    // zero pad cells
    if (tid == 0) *reinterpret_cast<float4*>(sx)        = make_float4(0,0,0,0);
    if (tid == 1) *reinterpret_cast<float4*>(sx + 4100) = make_float4(0,0,0,0);
    if (tid == 2) E[0] = 0;
    if (tid == 3) { E[1025] = 0; E[1026] = 0; }
    if (tid == 4) { O[0] = 0; O[1] = 0; }
    if (tid == 5) O[1026] = 0;
    if (tid == 6) HE[1024] = 0;
    if (tid == 7) HO[0] = 0;

    // stage x row: LDG.128 -> STS.128, lane-contiguous
    {
        const float4* x4 = reinterpret_cast<const float4*>(
            x + ((size_t)(b * 64 + cin) << 12));
        float4* sxw = reinterpret_cast<float4*>(sx + 4);
        #pragma unroll
        for (int p = 0; p < 4; ++p)
            sxw[tid + p * 256] = x4[tid + p * 256];
    }

    // phase-1 weights, BN folded
    float wk0[7], wk1[7], bias0, bias1;
    {
        const float inv0 = g1[oc0]     * rsqrtf(v1[oc0]     + 1e-5f);
        const float inv1 = g1[oc0 + 1] * rsqrtf(v1[oc0 + 1] + 1e-5f);
        #pragma unroll
        for (int k = 0; k < 7; ++k) {
            wk0[k] = w1[oc0 * 7 + k]     * inv0;
            wk1[k] = w1[oc0 * 7 + 7 + k] * inv1;
        }
        bias0 = b1[oc0]     - m1[oc0]     * inv0;
        bias1 = b1[oc0 + 1] - m1[oc0 + 1] * inv1;
    }

    __syncthreads();

    // ---- phase 1: 8 h / 4 pairs per thread-iter (T = tid, tid+256) ----
    {
        const float4* sxp = reinterpret_cast<const float4*>(sx) + 2 * tid;
        ull* Ep  = E  + 2 * tid;   // stores at +1, +2 (STS.64 x2)
        ull* Op  = O  + 2 * tid;   // store  at +2     (STS.128)
        ull* HEp = HE + 2 * tid;   // store  at +0     (STS.128)
        ull* HOp = HO + 2 * tid;   // stores at +1, +2 (STS.64 x2)

        #pragma unroll 1
        for (int p = 0; p < 2; ++p) {
            float4 f0 = sxp[0], f1 = sxp[1], f2 = sxp[2], f3 = sxp[3];
            float v[16] = {f0.x,f0.y,f0.z,f0.w, f1.x,f1.y,f1.z,f1.w,
                           f2.x,f2.y,f2.z,f2.w, f3.x,f3.y,f3.z,f3.w};
            // v[i] = x[8T-4+i]; h(8T+j) uses v[j+1..j+7]
            ull Lq[4], Hq[4];
            #pragma unroll
            for (int q = 0; q < 4; ++q) {
                float a0 = bias0, a1 = bias1, c0 = bias0, c1 = bias1;
                #pragma unroll
                for (int k = 0; k < 7; ++k) {
                    const float ve = v[2 * q + 1 + k];
                    const float vo = v[2 * q + 2 + k];
                    a0 = fmaf(ve, wk0[k], a0);
                    a1 = fmaf(ve, wk1[k], a1);
                    c0 = fmaf(vo, wk0[k], c0);
                    c1 = fmaf(vo, wk1[k], c1);
                }
                ull h0 = act2(pack2(a0, a1));
                ull h1 = act2(pack2(c0, c1));
                Lq[q] = add2_(h0, h1);
                Hq[q] = add2_(h0, neg2_(h1));
            }
            // pairs 4T..4T+3; even pairs -> E/HE, odd pairs -> O/HO
            Ep[1] = Lq[0];                                     // pair 4T
            Ep[2] = Lq[2];                                     // pair 4T+2
            *reinterpret_cast<ulonglong2*>(Op + 2) =
                make_ulonglong2(Lq[1], Lq[3]);                 // pairs 4T+1,4T+3
            *reinterpret_cast<ulonglong2*>(HEp) =
                make_ulonglong2(Hq[0], Hq[2]);                 // pairs 4T,4T+2
            HOp[1] = Hq[1];                                    // pair 4T+1
            HOp[2] = Hq[3];                                    // pair 4T+3
            sxp += 512; Ep += 512; Op += 512; HEp += 512; HOp += 512;
        }
    }

    // phase-2 weights packed per channel pair; 1/sqrt2 folded (w/2)
    ull wLp[7], wHp[3], wsp;
    #pragma unroll
    for (int k = 0; k < 7; ++k)
        wLp[k] = pack2(w2L[oc0 * 7 + k] * 0.5f, w2L[oc0 * 7 + 7 + k] * 0.5f);
    #pragma unroll
    for (int k = 0; k < 3; ++k)
        wHp[k] = pack2(w2H[oc0 * 3 + k] * 0.5f, w2H[oc0 * 3 + 3 + k] * 0.5f);
    wsp = pack2(wskip[oc0], wskip[oc0 + 1]);

    const ull A1 = dup2(0.505f);    // leaky(o) = .505 o + .495 |o|
    const ull B1 = dup2(0.495f);

    __syncthreads();

    // ---- phase 2: 4 output pairs per thread-iter (tp = tid, tid+256) ----
    {
        const ull* Ep  = E  + 2 * tid;
        const ull* Op  = O  + 2 * tid;
        const ull* HEp = HE + 2 * tid;
        const ull* HOp = HO + 2 * tid;
        const float4* skp = reinterpret_cast<const float4*>(sx) + 2 * tid + 1;
        float4* o0p = reinterpret_cast<float4*>(
            out + ((size_t)(b * 128 + oc0) << 12)) + 2 * tid;
        float4* o1p = o0p + 1024;                 // next channel row

        #pragma unroll 1
        for (int p = 0; p < 2; ++p) {
            // L windows: evens {P-2,P,P+2,P+4,P+6}, odds {P-3,P-1,P+1,P+3,P+5}
            ulonglong2 e01 = *reinterpret_cast<const ulonglong2*>(Ep);
            ulonglong2 e23 = *reinterpret_cast<const ulonglong2*>(Ep + 2);
            ull le4 = Ep[4];
            ulonglong2 o01 = *reinterpret_cast<const ulonglong2*>(Op);
            ulonglong2 o23 = *reinterpret_cast<const ulonglong2*>(Op + 2);
            ull lo4 = Op[4];
            ull le0 = e01.x, le1 = e01.y, le2 = e23.x, le3 = e23.y;
            ull lo0 = o01.x, lo1 = o01.y, lo2 = o23.x, lo3 = o23.y;

            ull y0, y1, y2, y3;
            y0 = mul2_(wLp[0], lo0);
            y0 = fma2_(wLp[1], le0, y0);
            y0 = fma2_(wLp[2], lo1, y0);
            y0 = fma2_(wLp[3], le1, y0);
            y0 = fma2_(wLp[4], lo2, y0);
            y0 = fma2_(wLp[5], le2, y0);
            y0 = fma2_(wLp[6], lo3, y0);
            y1 = mul2_(wLp[0], le0);
            y1 = fma2_(wLp[1], lo1, y1);
            y1 = fma2_(wLp[2], le1, y1);
            y1 = fma2_(wLp[3], lo2, y1);
            y1 = fma2_(wLp[4], le2, y1);
            y1 = fma2_(wLp[5], lo3, y1);
            y1 = fma2_(wLp[6], le3, y1);
            y2 = mul2_(wLp[0], lo1);
            y2 = fma2_(wLp[1], le1, y2);
            y2 = fma2_(wLp[2], lo2, y2);
            y2 = fma2_(wLp[3], le2, y2);
            y2 = fma2_(wLp[4], lo3, y2);
            y2 = fma2_(wLp[5], le3, y2);
            y2 = fma2_(wLp[6], lo4, y2);
            y3 = mul2_(wLp[0], le1);
            y3 = fma2_(wLp[1], lo2, y3);
            y3 = fma2_(wLp[2], le2, y3);
            y3 = fma2_(wLp[3], lo3, y3);
            y3 = fma2_(wLp[4], le3, y3);
            y3 = fma2_(wLp[5], lo4, y3);
            y3 = fma2_(wLp[6], le4, y3);

            // H windows: evens {P,P+2,P+4}, odds {P-1,P+1,P+3}
            ulonglong2 he01 = *reinterpret_cast<const ulonglong2*>(HEp);
            ull he2 = HEp[2];
            ulonglong2 ho01 = *reinterpret_cast<const ulonglong2*>(HOp);
            ull ho2 = HOp[2];
            ull he0 = he01.x, he1 = he01.y, ho0 = ho01.x, ho1 = ho01.y;

            ull z0, z1, z2, z3;
            z0 = mul2_(wHp[0], ho0);
            z0 = fma2_(wHp[1], he0, z0);
            z0 = fma2_(wHp[2], ho1, z0);
            z1 = mul2_(wHp[0], he0);
            z1 = fma2_(wHp[1], ho1, z1);
            z1 = fma2_(wHp[2], he1, z1);
            z2 = mul2_(wHp[0], ho1);
            z2 = fma2_(wHp[1], he1, z2);
            z2 = fma2_(wHp[2], ho2, z2);
            z3 = mul2_(wHp[0], he1);
            z3 = fma2_(wHp[1], ho2, z3);
            z3 = fma2_(wHp[2], he2, z3);

            // merge + skip + leaky
            const float4 s0 = skp[0];   // x[8tp   .. 8tp+3]
            const float4 s1 = skp[1];   // x[8tp+4 .. 8tp+7]
            ull e0 = add2_(y0, z0), d0 = add2_(y0, neg2_(z0));
            ull e1 = add2_(y1, z1), d1 = add2_(y1, neg2_(z1));
            ull e2 = add2_(y2, z2), d2 = add2_(y2, neg2_(z2));
            ull e3 = add2_(y3, z3), d3 = add2_(y3, neg2_(z3));
            e0 = fma2_(dup2(s0.x), wsp, e0);  d0 = fma2_(dup2(s0.y), wsp, d0);
            e1 = fma2_(dup2(s0.z), wsp, e1);  d1 = fma2_(dup2(s0.w), wsp, d1);
            e2 = fma2_(dup2(s1.x), wsp, e2);  d2 = fma2_(dup2(s1.y), wsp, d2);
            e3 = fma2_(dup2(s1.z), wsp, e3);  d3 = fma2_(dup2(s1.w), wsp, d3);
            e0 = fma2_(e0, A1, mul2_(abs2_(e0), B1));
            d0 = fma2_(d0, A1, mul2_(abs2_(d0), B1));
            e1 = fma2_(e1, A1, mul2_(abs2_(e1), B1));
            d1 = fma2_(d1, A1, mul2_(abs2_(d1), B1));
            e2 = fma2_(e2, A1, mul2_(abs2_(e2), B1));
            d2 = fma2_(d2, A1, mul2_(abs2_(d2), B1));
            e3 = fma2_(e3, A1, mul2_(abs2_(e3), B1));
            d3 = fma2_(d3, A1, mul2_(abs2_(d3), B1));

            float2 fe0 = unpack2(e0), fd0 = unpack2(d0);
            float2 fe1 = unpack2(e1), fd1 = unpack2(d1);
            float2 fe2 = unpack2(e2), fd2 = unpack2(d2);
            float2 fe3 = unpack2(e3), fd3 = unpack2(d3);
            o0p[0] = make_float4(fe0.x, fd0.x, fe1.x, fd1.x);
            o0p[1] = make_float4(fe2.x, fd2.x, fe3.x, fd3.x);
            o1p[0] = make_float4(fe0.y, fd0.y, fe1.y, fd1.y);
            o1p[1] = make_float4(fe2.y, fd2.y, fe3.y, fd3.y);

            Ep += 512; Op += 512; HEp += 512; HOp += 512;
            skp += 512; o0p += 512; o1p += 512;
        }
    }
}

extern "C" void kernel_launch(void* const* d_in, const int* in_sizes, int n_in,
                              void* d_out, int out_size) {
    const float* x     = (const float*)d_in[0];
    const float* w1    = (const float*)d_in[1];
    const float* g1    = (const float*)d_in[2];
    const float* b1    = (const float*)d_in[3];
    const float* m1    = (const float*)d_in[4];
    const float* v1    = (const float*)d_in[5];
    const float* w2L   = (const float*)d_in[6];
    const float* w2H   = (const float*)d_in[7];
    const float* wskip = (const float*)d_in[8];
    float* out = (float*)d_out;

    static bool attr_set = false;
    if (!attr_set) {
        cudaFuncSetAttribute(fused_block_wavelet_down,
                             cudaFuncAttributeMaxDynamicSharedMemorySize,
                             SMEM_BYTES);
        attr_set = true;
    }
    fused_block_wavelet_down<<<64 * 64, 256, SMEM_BYTES>>>(
        x, w1, g1, b1, m1, v1, w2L, w2H, wskip, out);
}

// round 11
// speedup vs baseline: 1.7186x; 1.0519x over previous
#include <cuda_runtime.h>

typedef unsigned long long ull;

// ---- f32x2 packed helpers (sm_100+) ----
__device__ __forceinline__ ull pack2(float lo, float hi) {
    ull r; asm("mov.b64 %0, {%1, %2};" : "=l"(r) : "f"(lo), "f"(hi)); return r;
}
__device__ __forceinline__ ull dup2(float v) {
    ull r; asm("mov.b64 %0, {%1, %1};" : "=l"(r) : "f"(v)); return r;
}
__device__ __forceinline__ float2 unpack2(ull v) {
    float2 r; asm("mov.b64 {%0, %1}, %2;" : "=f"(r.x), "=f"(r.y) : "l"(v)); return r;
}
__device__ __forceinline__ ull fma2_(ull a, ull b, ull c) {
    ull r; asm("fma.rn.f32x2 %0, %1, %2, %3;" : "=l"(r) : "l"(a), "l"(b), "l"(c)); return r;
}
__device__ __forceinline__ ull mul2_(ull a, ull b) {
    ull r; asm("mul.rn.f32x2 %0, %1, %2;" : "=l"(r) : "l"(a), "l"(b)); return r;
}
__device__ __forceinline__ ull add2_(ull a, ull b) {
    ull r; asm("add.rn.f32x2 %0, %1, %2;" : "=l"(r) : "l"(a), "l"(b)); return r;
}
__device__ __forceinline__ ull abs2_(ull a) {
    ull r; asm("and.b64 %0, %1, 0x7FFFFFFF7FFFFFFF;" : "=l"(r) : "l"(a)); return r;
}
__device__ __forceinline__ ull neg2_(ull a) {
    ull r; asm("xor.b64 %0, %1, 0x8000000080000000;" : "=l"(r) : "l"(a)); return r;
}
__device__ __forceinline__ float tanh_approx(float x) {
    float y; asm("tanh.approx.f32 %0, %1;" : "=f"(y) : "f"(x)); return y;
}

// packed tanh-GELU + leaky on pre-activation pair {ch0, ch1}
__device__ __forceinline__ ull act2(ull ap) {
    const ull K0 = dup2(0.79788456080286536f);
    const ull KK = dup2(0.79788456080286536f * 0.044715f);
    const ull A2 = dup2(0.2525f);   // leaky(0.5z) = .2525 z + .2475 |z|
    const ull B2 = dup2(0.2475f);
    ull x2 = mul2_(ap, ap);
    ull u  = mul2_(ap, fma2_(x2, KK, K0));       // k0*a*(1 + k1*a^2)
    float2 uv = unpack2(u);
    ull th = pack2(tanh_approx(uv.x), tanh_approx(uv.y));
    ull z  = fma2_(ap, th, ap);                  // a*(1+tanh) = 2*gelu
    return fma2_(z, A2, mul2_(abs2_(z), B2));
}

// Dynamic smem:
//   sx : floats 0..4103  (x[t] at sx[t+4]; zeros [0..3],[4100..4103])
//   band (ull base = smem+4104), contiguous sub-arrays addressed by constant
//   offsets off one pointer:
//     E  @ 0    len 1028 : L pair 2m   at [m+1]      ; zeros [0],[1025],[1026]
//     O  @ 1028 len 1028 : L pair 2m+1 at [1028+m+2] ; zeros [1028],[1029],[2054]
//     HE @ 2056 len 1026 : H pair 2m   at [2056+m]   ; zero  [3080]
//     HO @ 3082 len 1026 : H pair 2m+1 at [3082+m+1] ; zero  [3082]
// total = 16416 + 4108*8 = 49280 bytes
#define SMEM_BYTES 49280

// One CTA per (b, cin); outputs channels 2*cin, 2*cin+1. Even/odd band split
// (conflict-free, halved read redundancy) + register diet for 4 CTAs/SM.
__global__ __launch_bounds__(256, 4)
void fused_block_wavelet_down(
    const float* __restrict__ x,      // (64, 64, 4096)
    const float* __restrict__ w1,     // (128, 1, 7)
    const float* __restrict__ g1,
    const float* __restrict__ b1,
    const float* __restrict__ m1,
    const float* __restrict__ v1,
    const float* __restrict__ w2L,    // (128, 1, 7)
    const float* __restrict__ w2H,    // (128, 1, 3)
    const float* __restrict__ wskip,  // (128, 1, 1)
    float* __restrict__ out)          // (64, 128, 4096)
{
    extern __shared__ float smem[];
    float* sx = smem;
    ull* band = reinterpret_cast<ull*>(smem + 4104);

    const int tid = threadIdx.x;
    const int b   = blockIdx.x >> 6;
    const int cin = blockIdx.x & 63;
    const int oc0 = 2 * cin;

    // zero pad cells
    if (tid == 0) *reinterpret_cast<float4*>(sx)        = make_float4(0,0,0,0);
    if (tid == 1) *reinterpret_cast<float4*>(sx + 4100) = make_float4(0,0,0,0);
    if (tid == 2) band[0] = 0;
    if (tid == 3) { band[1025] = 0; band[1026] = 0; }
    if (tid == 4) { band[1028] = 0; band[1029] = 0; }
    if (tid == 5) band[2054] = 0;
    if (tid == 6) band[3080] = 0;
    if (tid == 7) band[3082] = 0;

    // stage x row: LDG.128 -> STS.128, lane-contiguous
    {
        const float4* x4 = reinterpret_cast<const float4*>(
            x + ((size_t)(b * 64 + cin) << 12));
        float4* sxw = reinterpret_cast<float4*>(sx + 4);
        #pragma unroll
        for (int p = 0; p < 4; ++p)
            sxw[tid + p * 256] = x4[tid + p * 256];
    }

    // phase-1 weights, BN folded
    float wk0[7], wk1[7], bias0, bias1;
    {
        const float inv0 = g1[oc0]     * rsqrtf(v1[oc0]     + 1e-5f);
        const float inv1 = g1[oc0 + 1] * rsqrtf(v1[oc0 + 1] + 1e-5f);
        #pragma unroll
        for (int k = 0; k < 7; ++k) {
            wk0[k] = w1[oc0 * 7 + k]     * inv0;
            wk1[k] = w1[oc0 * 7 + 7 + k] * inv1;
        }
        bias0 = b1[oc0]     - m1[oc0]     * inv0;
        bias1 = b1[oc0 + 1] - m1[oc0 + 1] * inv1;
    }

    __syncthreads();

    // ---- phase 1: 8 h / 4 pairs per thread-iter; immediate per-pair stores ----
    {
        const float4* sxp = reinterpret_cast<const float4*>(sx) + 2 * tid;
        ull* P = band + 2 * tid;

        #pragma unroll 1
        for (int p = 0; p < 2; ++p) {
            float4 f0 = sxp[0], f1 = sxp[1], f2 = sxp[2], f3 = sxp[3];
            float v[16] = {f0.x,f0.y,f0.z,f0.w, f1.x,f1.y,f1.z,f1.w,
                           f2.x,f2.y,f2.z,f2.w, f3.x,f3.y,f3.z,f3.w};
            // v[i] = x[8T-4+i]; h(8T+j) uses v[j+1..j+7]
            #pragma unroll
            for (int q = 0; q < 4; ++q) {
                float a0 = bias0, a1 = bias1, c0 = bias0, c1 = bias1;
                #pragma unroll
                for (int k = 0; k < 7; ++k) {
                    const float ve = v[2 * q + 1 + k];
                    const float vo = v[2 * q + 2 + k];
                    a0 = fmaf(ve, wk0[k], a0);
                    a1 = fmaf(ve, wk1[k], a1);
                    c0 = fmaf(vo, wk0[k], c0);
                    c1 = fmaf(vo, wk1[k], c1);
                }
                ull h0 = act2(pack2(a0, a1));
                ull h1 = act2(pack2(c0, c1));
                ull Lp = add2_(h0, h1);
                ull Hp = add2_(h0, neg2_(h1));
                // pair 4T+q -> even/odd sub-array, constant offsets
                if (q == 0)      { P[1]    = Lp; P[2056] = Hp; }
                else if (q == 1) { P[1030] = Lp; P[3083] = Hp; }
                else if (q == 2) { P[2]    = Lp; P[2057] = Hp; }
                else             { P[1031] = Lp; P[3084] = Hp; }
            }
            sxp += 512; P += 512;
        }
    }

    // phase-2 weights packed per channel pair; 1/sqrt2 folded (w/2)
    ull wLp[7], wHp[3], wsp;
    #pragma unroll
    for (int k = 0; k < 7; ++k)
        wLp[k] = pack2(w2L[oc0 * 7 + k] * 0.5f, w2L[oc0 * 7 + 7 + k] * 0.5f);
    #pragma unroll
    for (int k = 0; k < 3; ++k)
        wHp[k] = pack2(w2H[oc0 * 3 + k] * 0.5f, w2H[oc0 * 3 + 3 + k] * 0.5f);
    wsp = pack2(wskip[oc0], wskip[oc0 + 1]);

    const ull A1 = dup2(0.505f);    // leaky(o) = .505 o + .495 |o|
    const ull B1 = dup2(0.495f);

    __syncthreads();

    // ---- phase 2: 4 output pairs per thread-iter; H band first ----
    {
        const ull* P = band + 2 * tid;
        const float4* sxp = reinterpret_cast<const float4*>(sx) + 2 * tid + 1;
        float4* o0p = reinterpret_cast<float4*>(
            out + ((size_t)(b * 128 + oc0) << 12)) + 2 * tid;

        #pragma unroll 1
        for (int p = 0; p < 2; ++p) {
            // H windows: evens {P,P+2,P+4} -> HE[2tid..], odds -> HO[...]
            ulonglong2 heq = *reinterpret_cast<const ulonglong2*>(P + 2056);
            ull he2 = P[2058];
            ulonglong2 hoq = *reinterpret_cast<const ulonglong2*>(P + 3082);
            ull ho2 = P[3084];
            ull z0, z1, z2, z3;
            z0 = mul2_(wHp[0], hoq.x);
            z0 = fma2_(wHp[1], heq.x, z0);
            z0 = fma2_(wHp[2], hoq.y, z0);
            z1 = mul2_(wHp[0], heq.x);
            z1 = fma2_(wHp[1], hoq.y, z1);
            z1 = fma2_(wHp[2], heq.y, z1);
            z2 = mul2_(wHp[0], hoq.y);
            z2 = fma2_(wHp[1], heq.y, z2);
            z2 = fma2_(wHp[2], ho2,   z2);
            z3 = mul2_(wHp[0], heq.y);
            z3 = fma2_(wHp[1], ho2,   z3);
            z3 = fma2_(wHp[2], he2,   z3);

            // L windows (H regs now dead)
            ulonglong2 e01 = *reinterpret_cast<const ulonglong2*>(P);
            ulonglong2 e23 = *reinterpret_cast<const ulonglong2*>(P + 2);
            ull le4 = P[4];
            ulonglong2 o01 = *reinterpret_cast<const ulonglong2*>(P + 1028);
            ulonglong2 o23 = *reinterpret_cast<const ulonglong2*>(P + 1030);
            ull lo4 = P[1032];

            ull y0, y1, y2, y3;
            y0 = mul2_(wLp[0], o01.x);
            y0 = fma2_(wLp[1], e01.x, y0);
            y0 = fma2_(wLp[2], o01.y, y0);
            y0 = fma2_(wLp[3], e01.y, y0);
            y0 = fma2_(wLp[4], o23.x, y0);
            y0 = fma2_(wLp[5], e23.x, y0);
            y0 = fma2_(wLp[6], o23.y, y0);
            y1 = mul2_(wLp[0], e01.x);
            y1 = fma2_(wLp[1], o01.y, y1);
            y1 = fma2_(wLp[2], e01.y, y1);
            y1 = fma2_(wLp[3], o23.x, y1);
            y1 = fma2_(wLp[4], e23.x, y1);
            y1 = fma2_(wLp[5], o23.y, y1);
            y1 = fma2_(wLp[6], e23.y, y1);
            y2 = mul2_(wLp[0], o01.y);
            y2 = fma2_(wLp[1], e01.y, y2);
            y2 = fma2_(wLp[2], o23.x, y2);
            y2 = fma2_(wLp[3], e23.x, y2);
            y2 = fma2_(wLp[4], o23.y, y2);
            y2 = fma2_(wLp[5], e23.y, y2);
            y2 = fma2_(wLp[6], lo4,   y2);
            y3 = mul2_(wLp[0], e01.y);
            y3 = fma2_(wLp[1], o23.x, y3);
            y3 = fma2_(wLp[2], e23.x, y3);
            y3 = fma2_(wLp[3], o23.y, y3);
            y3 = fma2_(wLp[4], e23.y, y3);
            y3 = fma2_(wLp[5], lo4,   y3);
            y3 = fma2_(wLp[6], le4,   y3);

            // merge + skip + leaky
            const float4 s0 = sxp[0];   // x[8tp   .. 8tp+3]
            const float4 s1 = sxp[1];   // x[8tp+4 .. 8tp+7]
            ull e0 = add2_(y0, z0), d0 = add2_(y0, neg2_(z0));
            ull e1 = add2_(y1, z1), d1 = add2_(y1, neg2_(z1));
            ull e2 = add2_(y2, z2), d2 = add2_(y2, neg2_(z2));
            ull e3 = add2_(y3, z3), d3 = add2_(y3, neg2_(z3));
            e0 = fma2_(dup2(s0.x), wsp, e0);  d0 = fma2_(dup2(s0.y), wsp, d0);
            e1 = fma2_(dup2(s0.z), wsp, e1);  d1 = fma2_(dup2(s0.w), wsp, d1);
            e2 = fma2_(dup2(s1.x), wsp, e2);  d2 = fma2_(dup2(s1.y), wsp, d2);
            e3 = fma2_(dup2(s1.z), wsp, e3);  d3 = fma2_(dup2(s1.w), wsp, d3);
            e0 = fma2_(e0, A1, mul2_(abs2_(e0), B1));
            d0 = fma2_(d0, A1, mul2_(abs2_(d0), B1));
            e1 = fma2_(e1, A1, mul2_(abs2_(e1), B1));
            d1 = fma2_(d1, A1, mul2_(abs2_(d1), B1));
            e2 = fma2_(e2, A1, mul2_(abs2_(e2), B1));
            d2 = fma2_(d2, A1, mul2_(abs2_(d2), B1));
            e3 = fma2_(e3, A1, mul2_(abs2_(e3), B1));
            d3 = fma2_(d3, A1, mul2_(abs2_(d3), B1));

            float2 fe0 = unpack2(e0), fd0 = unpack2(d0);
            float2 fe1 = unpack2(e1), fd1 = unpack2(d1);
            float2 fe2 = unpack2(e2), fd2 = unpack2(d2);
            float2 fe3 = unpack2(e3), fd3 = unpack2(d3);
            o0p[0]    = make_float4(fe0.x, fd0.x, fe1.x, fd1.x);
            o0p[1]    = make_float4(fe2.x, fd2.x, fe3.x, fd3.x);
            o0p[1024] = make_float4(fe0.y, fd0.y, fe1.y, fd1.y);  // channel 1 row
            o0p[1025] = make_float4(fe2.y, fd2.y, fe3.y, fd3.y);

            P += 512; sxp += 512; o0p += 512;
        }
    }
}

extern "C" void kernel_launch(void* const* d_in, const int* in_sizes, int n_in,
                              void* d_out, int out_size) {
    const float* x     = (const float*)d_in[0];
    const float* w1    = (const float*)d_in[1];
    const float* g1    = (const float*)d_in[2];
    const float* b1    = (const float*)d_in[3];
    const float* m1    = (const float*)d_in[4];
    const float* v1    = (const float*)d_in[5];
    const float* w2L   = (const float*)d_in[6];
    const float* w2H   = (const float*)d_in[7];
    const float* wskip = (const float*)d_in[8];
    float* out = (float*)d_out;

    static bool attr_set = false;
    if (!attr_set) {
        cudaFuncSetAttribute(fused_block_wavelet_down,
                             cudaFuncAttributeMaxDynamicSharedMemorySize,
                             SMEM_BYTES);
        attr_set = true;
    }
    fused_block_wavelet_down<<<64 * 64, 256, SMEM_BYTES>>>(
        x, w1, g1, b1, m1, v1, w2L, w2H, wskip, out);
}

// round 13
// speedup vs baseline: 1.7196x; 1.0006x over previous
#include <cuda_runtime.h>

typedef unsigned long long ull;

// ---- f32x2 packed helpers (sm_100+) ----
__device__ __forceinline__ ull pack2(float lo, float hi) {
    ull r; asm("mov.b64 %0, {%1, %2};" : "=l"(r) : "f"(lo), "f"(hi)); return r;
}
__device__ __forceinline__ ull dup2(float v) {
    ull r; asm("mov.b64 %0, {%1, %1};" : "=l"(r) : "f"(v)); return r;
}
__device__ __forceinline__ float2 unpack2(ull v) {
    float2 r; asm("mov.b64 {%0, %1}, %2;" : "=f"(r.x), "=f"(r.y) : "l"(v)); return r;
}
__device__ __forceinline__ ull fma2_(ull a, ull b, ull c) {
    ull r; asm("fma.rn.f32x2 %0, %1, %2, %3;" : "=l"(r) : "l"(a), "l"(b), "l"(c)); return r;
}
__device__ __forceinline__ ull mul2_(ull a, ull b) {
    ull r; asm("mul.rn.f32x2 %0, %1, %2;" : "=l"(r) : "l"(a), "l"(b)); return r;
}
__device__ __forceinline__ ull add2_(ull a, ull b) {
    ull r; asm("add.rn.f32x2 %0, %1, %2;" : "=l"(r) : "l"(a), "l"(b)); return r;
}
__device__ __forceinline__ ull abs2_(ull a) {
    ull r; asm("and.b64 %0, %1, 0x7FFFFFFF7FFFFFFF;" : "=l"(r) : "l"(a)); return r;
}
__device__ __forceinline__ ull neg2_(ull a) {
    ull r; asm("xor.b64 %0, %1, 0x8000000080000000;" : "=l"(r) : "l"(a)); return r;
}
__device__ __forceinline__ float tanh_approx(float x) {
    float y; asm("tanh.approx.f32 %0, %1;" : "=f"(y) : "f"(x)); return y;
}

// packed tanh-GELU + leaky on pre-activation pair {ch0, ch1}
__device__ __forceinline__ ull act2(ull ap) {
    const ull K0 = dup2(0.79788456080286536f);
    const ull KK = dup2(0.79788456080286536f * 0.044715f);
    const ull A2 = dup2(0.2525f);   // leaky(0.5z) = .2525 z + .2475 |z|
    const ull B2 = dup2(0.2475f);
    ull x2 = mul2_(ap, ap);
    ull u  = mul2_(ap, fma2_(x2, KK, K0));       // k0*a*(1 + k1*a^2)
    float2 uv = unpack2(u);
    ull th = pack2(tanh_approx(uv.x), tanh_approx(uv.y));
    ull z  = fma2_(ap, th, ap);                  // a*(1+tanh) = 2*gelu
    return fma2_(z, A2, mul2_(abs2_(z), B2));
}

// Grid 8192 = (b, cin, half). CTA handles half a row: 1024 output pairs.
// Static smem (24.8 KB):
//   sx[2072]  : x local t in [-12,2059] at sx[t+12]; halo from neighbor/zeros
//   LB[1032]  : L band pair m (local, [-3..1026]) at LB[m+4], {ch0,ch1} ull
//   HB[1028]  : H band pair m ([-1..1025]) at HB[m+2]
// All hot accesses are 16B-stride (conflict-free) LDS/STS.128.
__global__ __launch_bounds__(256, 5)
void fused_block_wavelet_down(
    const float* __restrict__ x,      // (64, 64, 4096)
    const float* __restrict__ w1,     // (128, 1, 7)
    const float* __restrict__ g1,
    const float* __restrict__ b1,
    const float* __restrict__ m1,
    const float* __restrict__ v1,
    const float* __restrict__ w2L,    // (128, 1, 7)
    const float* __restrict__ w2H,    // (128, 1, 3)
    const float* __restrict__ wskip,  // (128, 1, 1)
    float* __restrict__ out)          // (64, 128, 4096)
{
    __shared__ float sx[2072];
    __shared__ ull   LB[1032];
    __shared__ ull   HB[1028];

    const int tid  = threadIdx.x;
    const int bx   = blockIdx.x;
    const int half = bx & 1;
    const int cin  = (bx >> 1) & 63;
    const int b    = bx >> 7;
    const int oc0  = 2 * cin;

    // ---- stage x half-row + 12-float halos (zeros at true row edges) ----
    {
        const float4* x4 = reinterpret_cast<const float4*>(
            x + ((size_t)(b * 64 + cin) << 12)) + half * 512;
        float4* s4 = reinterpret_cast<float4*>(sx);
        #pragma unroll
        for (int p = 0; p < 2; ++p)
            s4[3 + tid + p * 256] = x4[tid + p * 256];
        if (tid < 3) {
            s4[tid] = half ? x4[tid - 3] : make_float4(0, 0, 0, 0);
        } else if (tid < 6) {
            s4[512 + tid] = half ? make_float4(0, 0, 0, 0) : x4[509 + tid];
        }
    }

    // phase-1 weights, BN folded
    float wk0[7], wk1[7], bias0, bias1;
    {
        const float inv0 = g1[oc0]     * rsqrtf(v1[oc0]     + 1e-5f);
        const float inv1 = g1[oc0 + 1] * rsqrtf(v1[oc0 + 1] + 1e-5f);
        #pragma unroll
        for (int k = 0; k < 7; ++k) {
            wk0[k] = w1[oc0 * 7 + k]     * inv0;
            wk1[k] = w1[oc0 * 7 + 7 + k] * inv1;
        }
        bias0 = b1[oc0]     - m1[oc0]     * inv0;
        bias1 = b1[oc0 + 1] - m1[oc0 + 1] * inv1;
    }

    __syncthreads();

    // ---- phase 1: conv7(+BN) + GELU + leaky + Haar, pairs 2tp, 2tp+1 ----
    {
        const float4* sxp = reinterpret_cast<const float4*>(sx) + tid + 2;
        ull* Lw = LB + 2 * tid + 4;
        ull* Hw = HB + 2 * tid + 2;

        #pragma unroll 1
        for (int p = 0; p < 2; ++p) {
            float4 f0 = sxp[0], f1 = sxp[1], f2 = sxp[2];
            float v[12] = {f0.x,f0.y,f0.z,f0.w, f1.x,f1.y,f1.z,f1.w,
                           f2.x,f2.y,f2.z,f2.w};   // v[i] = x_loc(4tp-4+i)
            ull hp[4];
            #pragma unroll
            for (int j = 0; j < 4; ++j) {
                float a0 = bias0, a1 = bias1;
                #pragma unroll
                for (int k = 0; k < 7; ++k) {
                    a0 = fmaf(v[1 + j + k], wk0[k], a0);
                    a1 = fmaf(v[1 + j + k], wk1[k], a1);
                }
                hp[j] = act2(pack2(a0, a1));
            }
            *reinterpret_cast<ulonglong2*>(Lw) = make_ulonglong2(
                add2_(hp[0], hp[1]), add2_(hp[2], hp[3]));
            *reinterpret_cast<ulonglong2*>(Hw) = make_ulonglong2(
                add2_(hp[0], neg2_(hp[1])), add2_(hp[2], neg2_(hp[3])));
            sxp += 256; Lw += 512; Hw += 512;
        }

        // seam/edge pairs: threads 0..5 handle L m = -3,-2,-1,1024,1025,1026
        // (H for m = -1,1024,1025). True row edges store zeros (conv2 pad).
        if (tid < 6) {
            const int m = (tid < 3) ? (tid - 3) : (1021 + tid);
            const bool zero = half ? (tid >= 3) : (tid < 3);
            ull Lp = 0, Hp = 0;
            if (!zero) {
                float a0 = bias0, a1 = bias1, c0 = bias0, c1 = bias1;
                #pragma unroll
                for (int k = 0; k < 7; ++k) {
                    const float xe = sx[2 * m + 9 + k];    // x_loc(2m-3+k)
                    const float xo = sx[2 * m + 10 + k];   // x_loc(2m-2+k)
                    a0 = fmaf(xe, wk0[k], a0);
                    a1 = fmaf(xe, wk1[k], a1);
                    c0 = fmaf(xo, wk0[k], c0);
                    c1 = fmaf(xo, wk1[k], c1);
                }
                ull h0 = act2(pack2(a0, a1));
                ull h1 = act2(pack2(c0, c1));
                Lp = add2_(h0, h1);
                Hp = add2_(h0, neg2_(h1));
            }
            LB[m + 4] = Lp;
            if (tid >= 2 && tid <= 4) HB[m + 2] = Hp;
        }
    }

    // phase-2 weights packed per channel pair; 1/sqrt2 folded (w/2)
    ull wLp[7], wHp[3], wsp;
    #pragma unroll
    for (int k = 0; k < 7; ++k)
        wLp[k] = pack2(w2L[oc0 * 7 + k] * 0.5f, w2L[oc0 * 7 + 7 + k] * 0.5f);
    #pragma unroll
    for (int k = 0; k < 3; ++k)
        wHp[k] = pack2(w2H[oc0 * 3 + k] * 0.5f, w2H[oc0 * 3 + 3 + k] * 0.5f);
    wsp = pack2(wskip[oc0], wskip[oc0 + 1]);

    const ull A1 = dup2(0.505f);    // leaky(o) = .505 o + .495 |o|
    const ull B1 = dup2(0.495f);

    __syncthreads();

    // ---- phase 2: conv7L/conv3H + merge + skip + leaky, pairs 2tp, 2tp+1 ----
    {
        const ulonglong2* LA = reinterpret_cast<const ulonglong2*>(LB) + tid;
        const ulonglong2* HA = reinterpret_cast<const ulonglong2*>(HB) + tid;
        const float4* skp = reinterpret_cast<const float4*>(sx) + tid + 3;
        float4* o0p = reinterpret_cast<float4*>(
            out + ((size_t)(b * 128 + oc0) << 12)) + half * 512 + tid;

        #pragma unroll 1
        for (int p = 0; p < 2; ++p) {
            // lp[i] = LB[2tp+i] = L pair (2tp+i-4); consume i = 1..8
            ulonglong2 q0 = LA[0], q1 = LA[1], q2 = LA[2], q3 = LA[3], q4 = LA[4];
            ull lp[10] = {q0.x,q0.y, q1.x,q1.y, q2.x,q2.y, q3.x,q3.y, q4.x,q4.y};
            ull yLA = mul2_(wLp[0], lp[1]);
            ull yLB = mul2_(wLp[0], lp[2]);
            #pragma unroll
            for (int j = 1; j < 7; ++j) {
                yLA = fma2_(wLp[j], lp[1 + j], yLA);
                yLB = fma2_(wLp[j], lp[2 + j], yLB);
            }

            // hq[i] = HB[2tp+i] = H pair (2tp+i-2); consume i = 1..4
            ulonglong2 h0 = HA[0], h1 = HA[1], h2 = HA[2];
            ull hq[6] = {h0.x,h0.y, h1.x,h1.y, h2.x,h2.y};
            ull zA = mul2_(wHp[0], hq[1]);
            ull zB = mul2_(wHp[0], hq[2]);
            #pragma unroll
            for (int j = 1; j < 3; ++j) {
                zA = fma2_(wHp[j], hq[1 + j], zA);
                zB = fma2_(wHp[j], hq[2 + j], zB);
            }

            const float4 sk = skp[0];               // x_loc(4tp .. 4tp+3)
            ull eA = add2_(yLA, zA), dA = add2_(yLA, neg2_(zA));
            ull eB = add2_(yLB, zB), dB = add2_(yLB, neg2_(zB));
            eA = fma2_(dup2(sk.x), wsp, eA);
            dA = fma2_(dup2(sk.y), wsp, dA);
            eB = fma2_(dup2(sk.z), wsp, eB);
            dB = fma2_(dup2(sk.w), wsp, dB);
            eA = fma2_(eA, A1, mul2_(abs2_(eA), B1));
            dA = fma2_(dA, A1, mul2_(abs2_(dA), B1));
            eB = fma2_(eB, A1, mul2_(abs2_(eB), B1));
            dB = fma2_(dB, A1, mul2_(abs2_(dB), B1));

            float2 ea = unpack2(eA), da = unpack2(dA);
            float2 eb = unpack2(eB), db = unpack2(dB);
            o0p[0]    = make_float4(ea.x, da.x, eb.x, db.x);
            o0p[1024] = make_float4(ea.y, da.y, eb.y, db.y);   // channel 1 row

            LA += 256; HA += 256; skp += 256; o0p += 256;
        }
    }
}

extern "C" void kernel_launch(void* const* d_in, const int* in_sizes, int n_in,
                              void* d_out, int out_size) {
    const float* x     = (const float*)d_in[0];
    const float* w1    = (const float*)d_in[1];
    const float* g1    = (const float*)d_in[2];
    const float* b1    = (const float*)d_in[3];
    const float* m1    = (const float*)d_in[4];
    const float* v1    = (const float*)d_in[5];
    const float* w2L   = (const float*)d_in[6];
    const float* w2H   = (const float*)d_in[7];
    const float* wskip = (const float*)d_in[8];
    float* out = (float*)d_out;

    fused_block_wavelet_down<<<64 * 64 * 2, 256>>>(
        x, w1, g1, b1, m1, v1, w2L, w2H, wskip, out);
}

// round 14
// speedup vs baseline: 1.7245x; 1.0029x over previous
#include <cuda_runtime.h>

typedef unsigned long long ull;

// ---- f32x2 packed helpers (sm_100+) ----
__device__ __forceinline__ ull pack2(float lo, float hi) {
    ull r; asm("mov.b64 %0, {%1, %2};" : "=l"(r) : "f"(lo), "f"(hi)); return r;
}
__device__ __forceinline__ ull dup2(float v) {
    ull r; asm("mov.b64 %0, {%1, %1};" : "=l"(r) : "f"(v)); return r;
}
__device__ __forceinline__ float2 unpack2(ull v) {
    float2 r; asm("mov.b64 {%0, %1}, %2;" : "=f"(r.x), "=f"(r.y) : "l"(v)); return r;
}
__device__ __forceinline__ ull fma2_(ull a, ull b, ull c) {
    ull r; asm("fma.rn.f32x2 %0, %1, %2, %3;" : "=l"(r) : "l"(a), "l"(b), "l"(c)); return r;
}
__device__ __forceinline__ ull mul2_(ull a, ull b) {
    ull r; asm("mul.rn.f32x2 %0, %1, %2;" : "=l"(r) : "l"(a), "l"(b)); return r;
}
__device__ __forceinline__ ull add2_(ull a, ull b) {
    ull r; asm("add.rn.f32x2 %0, %1, %2;" : "=l"(r) : "l"(a), "l"(b)); return r;
}
__device__ __forceinline__ ull abs2_(ull a) {
    ull r; asm("and.b64 %0, %1, 0x7FFFFFFF7FFFFFFF;" : "=l"(r) : "l"(a)); return r;
}
__device__ __forceinline__ ull neg2_(ull a) {
    ull r; asm("xor.b64 %0, %1, 0x8000000080000000;" : "=l"(r) : "l"(a)); return r;
}
__device__ __forceinline__ float tanh_approx(float x) {
    float y; asm("tanh.approx.f32 %0, %1;" : "=f"(y) : "f"(x)); return y;
}

// packed tanh-GELU + leaky on pre-activation pair {ch0, ch1}
__device__ __forceinline__ ull act2(ull ap) {
    const ull K0 = dup2(0.79788456080286536f);
    const ull KK = dup2(0.79788456080286536f * 0.044715f);
    const ull A2 = dup2(0.2525f);   // leaky(0.5z) = .2525 z + .2475 |z|
    const ull B2 = dup2(0.2475f);
    ull x2 = mul2_(ap, ap);
    ull u  = mul2_(ap, fma2_(x2, KK, K0));       // k0*a*(1 + k1*a^2)
    float2 uv = unpack2(u);
    ull th = pack2(tanh_approx(uv.x), tanh_approx(uv.y));
    ull z  = fma2_(ap, th, ap);                  // a*(1+tanh) = 2*gelu
    return fma2_(z, A2, mul2_(abs2_(z), B2));
}

// Grid 8192 = (b, cin, half). CTA = half a row (1024 output pairs), 256 thr.
// No x staging: phase 1 reads its window straight from global (L1-cached);
// the phase-2 skip values ride in registers across the phase boundary.
// Static smem 16.5 KB: band arrays only, all hot accesses LDS/STS.128 CF.
//   LB[1032] : L pair m (local, [-3..1026]) at LB[m+4], {ch0,ch1} ull
//   HB[1028] : H pair m ([-1..1025]) at HB[m+2]
__global__ __launch_bounds__(256, 4)
void fused_block_wavelet_down(
    const float* __restrict__ x,      // (64, 64, 4096)
    const float* __restrict__ w1,     // (128, 1, 7)
    const float* __restrict__ g1,
    const float* __restrict__ b1,
    const float* __restrict__ m1,
    const float* __restrict__ v1,
    const float* __restrict__ w2L,    // (128, 1, 7)
    const float* __restrict__ w2H,    // (128, 1, 3)
    const float* __restrict__ wskip,  // (128, 1, 1)
    float* __restrict__ out)          // (64, 128, 4096)
{
    __shared__ __align__(16) ull LB[1032];
    __shared__ __align__(16) ull HB[1028];

    const int tid  = threadIdx.x;
    const int bx   = blockIdx.x;
    const int half = bx & 1;
    const int cin  = (bx >> 1) & 63;
    const int b    = bx >> 7;
    const int oc0  = 2 * cin;

    const float* xrow = x + ((size_t)(b * 64 + cin) << 12);   // full row
    const float4* xr4 = reinterpret_cast<const float4*>(xrow);

    // phase-1 weights, BN folded
    float wk0[7], wk1[7], bias0, bias1;
    {
        const float inv0 = g1[oc0]     * rsqrtf(v1[oc0]     + 1e-5f);
        const float inv1 = g1[oc0 + 1] * rsqrtf(v1[oc0 + 1] + 1e-5f);
        #pragma unroll
        for (int k = 0; k < 7; ++k) {
            wk0[k] = w1[oc0 * 7 + k]     * inv0;
            wk1[k] = w1[oc0 * 7 + 7 + k] * inv1;
        }
        bias0 = b1[oc0]     - m1[oc0]     * inv0;
        bias1 = b1[oc0 + 1] - m1[oc0 + 1] * inv1;
    }

    float4 skreg[2];   // x(4tp..4tp+3) per iter — phase-2 skip values

    // ---- phase 1: conv7(+BN) + GELU + leaky + Haar, pairs 2tp, 2tp+1 ----
    {
        #pragma unroll
        for (int p = 0; p < 2; ++p) {
            const int tp = tid + p * 256;             // 0..511
            const int g1i = half * 512 + tp;          // center float4 idx
            const float4 z4 = make_float4(0, 0, 0, 0);
            float4 f0 = (g1i - 1 >= 0)   ? xr4[g1i - 1] : z4;
            float4 f1 = xr4[g1i];
            float4 f2 = (g1i + 1 <= 1023) ? xr4[g1i + 1] : z4;
            skreg[p] = f1;

            float v[12] = {f0.x,f0.y,f0.z,f0.w, f1.x,f1.y,f1.z,f1.w,
                           f2.x,f2.y,f2.z,f2.w};      // v[i] = x_loc(4tp-4+i)
            ull hp[4];
            #pragma unroll
            for (int j = 0; j < 4; ++j) {
                float a0 = bias0, a1 = bias1;
                #pragma unroll
                for (int k = 0; k < 7; ++k) {
                    a0 = fmaf(v[1 + j + k], wk0[k], a0);
                    a1 = fmaf(v[1 + j + k], wk1[k], a1);
                }
                hp[j] = act2(pack2(a0, a1));
            }
            *reinterpret_cast<ulonglong2*>(LB + 2 * tp + 4) = make_ulonglong2(
                add2_(hp[0], hp[1]), add2_(hp[2], hp[3]));
            *reinterpret_cast<ulonglong2*>(HB + 2 * tp + 2) = make_ulonglong2(
                add2_(hp[0], neg2_(hp[1])), add2_(hp[2], neg2_(hp[3])));
        }

        // seam/edge pairs: threads 0..5 -> L m = -3,-2,-1,1024,1025,1026
        // (H for m = -1,1024,1025). True row edges store zeros (conv2 pad).
        if (tid < 6) {
            const int m = (tid < 3) ? (tid - 3) : (1021 + tid);
            const bool zero = half ? (tid >= 3) : (tid < 3);
            ull Lp = 0, Hp = 0;
            if (!zero) {
                // h(2m), h(2m+1); x global t = half*2048 + 2m - 3 + k (valid)
                const float* xg = xrow + half * 2048 + 2 * m - 3;
                float a0 = bias0, a1 = bias1, c0 = bias0, c1 = bias1;
                #pragma unroll
                for (int k = 0; k < 7; ++k) {
                    const float xe = xg[k];
                    const float xo = xg[k + 1];
                    a0 = fmaf(xe, wk0[k], a0);
                    a1 = fmaf(xe, wk1[k], a1);
                    c0 = fmaf(xo, wk0[k], c0);
                    c1 = fmaf(xo, wk1[k], c1);
                }
                ull h0 = act2(pack2(a0, a1));
                ull h1 = act2(pack2(c0, c1));
                Lp = add2_(h0, h1);
                Hp = add2_(h0, neg2_(h1));
            }
            LB[m + 4] = Lp;
            if (tid >= 2 && tid <= 4) HB[m + 2] = Hp;
        }
    }

    // phase-2 weights packed per channel pair; 1/sqrt2 folded (w/2)
    ull wLp[7], wHp[3], wsp;
    #pragma unroll
    for (int k = 0; k < 7; ++k)
        wLp[k] = pack2(w2L[oc0 * 7 + k] * 0.5f, w2L[oc0 * 7 + 7 + k] * 0.5f);
    #pragma unroll
    for (int k = 0; k < 3; ++k)
        wHp[k] = pack2(w2H[oc0 * 3 + k] * 0.5f, w2H[oc0 * 3 + 3 + k] * 0.5f);
    wsp = pack2(wskip[oc0], wskip[oc0 + 1]);

    const ull A1 = dup2(0.505f);    // leaky(o) = .505 o + .495 |o|
    const ull B1 = dup2(0.495f);

    __syncthreads();

    // ---- phase 2: conv7L/conv3H + merge + skip(regs) + leaky ----
    {
        const ulonglong2* LA = reinterpret_cast<const ulonglong2*>(LB) + tid;
        const ulonglong2* HA = reinterpret_cast<const ulonglong2*>(HB) + tid;
        float4* o0p = reinterpret_cast<float4*>(
            out + ((size_t)(b * 128 + oc0) << 12)) + half * 512 + tid;

        #pragma unroll
        for (int p = 0; p < 2; ++p) {
            // lp[i] = LB[2tp+i] = L pair (2tp+i-4); consume i = 1..8
            ulonglong2 q0 = LA[0], q1 = LA[1], q2 = LA[2], q3 = LA[3], q4 = LA[4];
            ull lp[10] = {q0.x,q0.y, q1.x,q1.y, q2.x,q2.y, q3.x,q3.y, q4.x,q4.y};
            ull yLA = mul2_(wLp[0], lp[1]);
            ull yLB = mul2_(wLp[0], lp[2]);
            #pragma unroll
            for (int j = 1; j < 7; ++j) {
                yLA = fma2_(wLp[j], lp[1 + j], yLA);
                yLB = fma2_(wLp[j], lp[2 + j], yLB);
            }

            // hq[i] = HB[2tp+i] = H pair (2tp+i-2); consume i = 1..4
            ulonglong2 h0 = HA[0], h1 = HA[1], h2 = HA[2];
            ull hq[6] = {h0.x,h0.y, h1.x,h1.y, h2.x,h2.y};
            ull zA = mul2_(wHp[0], hq[1]);
            ull zB = mul2_(wHp[0], hq[2]);
            #pragma unroll
            for (int j = 1; j < 3; ++j) {
                zA = fma2_(wHp[j], hq[1 + j], zA);
                zB = fma2_(wHp[j], hq[2 + j], zB);
            }

            const float4 sk = skreg[p];             // x_loc(4tp .. 4tp+3)
            ull eA = add2_(yLA, zA), dA = add2_(yLA, neg2_(zA));
            ull eB = add2_(yLB, zB), dB = add2_(yLB, neg2_(zB));
            eA = fma2_(dup2(sk.x), wsp, eA);
            dA = fma2_(dup2(sk.y), wsp, dA);
            eB = fma2_(dup2(sk.z), wsp, eB);
            dB = fma2_(dup2(sk.w), wsp, dB);
            eA = fma2_(eA, A1, mul2_(abs2_(eA), B1));
            dA = fma2_(dA, A1, mul2_(abs2_(dA), B1));
            eB = fma2_(eB, A1, mul2_(abs2_(eB), B1));
            dB = fma2_(dB, A1, mul2_(abs2_(dB), B1));

            float2 ea = unpack2(eA), da = unpack2(dA);
            float2 eb = unpack2(eB), db = unpack2(dB);
            o0p[0]    = make_float4(ea.x, da.x, eb.x, db.x);
            o0p[1024] = make_float4(ea.y, da.y, eb.y, db.y);   // channel 1 row

            LA += 256; HA += 256; o0p += 256;
        }
    }
}

extern "C" void kernel_launch(void* const* d_in, const int* in_sizes, int n_in,
                              void* d_out, int out_size) {
    const float* x     = (const float*)d_in[0];
    const float* w1    = (const float*)d_in[1];
    const float* g1    = (const float*)d_in[2];
    const float* b1    = (const float*)d_in[3];
    const float* m1    = (const float*)d_in[4];
    const float* v1    = (const float*)d_in[5];
    const float* w2L   = (const float*)d_in[6];
    const float* w2H   = (const float*)d_in[7];
    const float* wskip = (const float*)d_in[8];
    float* out = (float*)d_out;

    fused_block_wavelet_down<<<64 * 64 * 2, 256>>>(
        x, w1, g1, b1, m1, v1, w2L, w2H, wskip, out);
}